// round 1
// baseline (speedup 1.0000x reference)
#include <cuda_runtime.h>
#include <cuda_bf16.h>
#include <math.h>

#define Dm 768
#define Hh 12
#define DH 64
#define DEPTH 12
#define WARM 2
#define Kk 64
#define MLPD 3072
#define NTOK 197
#define NSEL 65
#define Bb 32

// ---------------- scratch (device globals; no allocation) ----------------
__device__ float g_X[Bb * NTOK * Dm];        // main activations (warm phase)
__device__ float g_Hbuf[Bb * NTOK * Dm];     // LN output / attention output
__device__ float g_QKV[Bb * NTOK * 3 * Dm];  // qkv; also reused as im2col buffer
__device__ float g_F1[Bb * NTOK * MLPD];     // fc1 output; also patch-gemm output
__device__ float g_Wt[Dm * Dm];              // transposed patch weight
__device__ float g_scores[Bb * NTOK];
__device__ int   g_idx[Bb * NSEL];
__device__ float g_Xr[Bb * NSEL * Dm];       // refined activations

// ---------------- helpers ----------------
__device__ __forceinline__ float gelu_exact(float x) {
    return 0.5f * x * (1.0f + erff(x * 0.70710678118654752440f));
}
__device__ __forceinline__ float warp_sum(float v) {
    #pragma unroll
    for (int o = 16; o; o >>= 1) v += __shfl_xor_sync(0xFFFFFFFFu, v, o);
    return v;
}

// ---------------- SGEMM 128x128x16, 256 thr, 8x8 microtile ----------------
// C[M,N] = A[M,K] @ B[K,N] + bias ; EPI: 0=bias, 1=bias+residual(Cin), 2=bias+GELU
// Requires: K % 16 == 0, N % 128 == 0. M guarded.
#define BM 128
#define BN 128
#define BKK 16
template<int EPI>
__global__ void sgemm_kernel(const float* __restrict__ A, const float* __restrict__ B,
                             const float* __restrict__ bias, const float* __restrict__ Cin,
                             float* __restrict__ Cout, int M, int N, int K) {
    __shared__ float As[BKK][BM];
    __shared__ float Bs[BKK][BN];
    const int tid = threadIdx.x;
    const int blockRow = blockIdx.y * BM;
    const int blockCol = blockIdx.x * BN;
    const int tRow = (tid / 16) * 8;
    const int tCol = (tid % 16) * 8;
    const int aRow = tid / 4;
    const int aCol = (tid % 4) * 4;
    const int bRow = tid / 32;
    const int bCol = (tid % 32) * 4;

    float acc[8][8];
    #pragma unroll
    for (int i = 0; i < 8; i++)
        #pragma unroll
        for (int j = 0; j < 8; j++) acc[i][j] = 0.f;

    for (int k0 = 0; k0 < K; k0 += BKK) {
        #pragma unroll
        for (int i = 0; i < 2; i++) {
            int r = aRow + i * 64;
            int gr = blockRow + r;
            float4 v = make_float4(0.f, 0.f, 0.f, 0.f);
            if (gr < M) v = *(const float4*)(A + (size_t)gr * K + k0 + aCol);
            As[aCol + 0][r] = v.x; As[aCol + 1][r] = v.y;
            As[aCol + 2][r] = v.z; As[aCol + 3][r] = v.w;
        }
        #pragma unroll
        for (int i = 0; i < 2; i++) {
            int r = bRow + i * 8;
            float4 v = *(const float4*)(B + (size_t)(k0 + r) * N + blockCol + bCol);
            *(float4*)&Bs[r][bCol] = v;
        }
        __syncthreads();
        #pragma unroll
        for (int kk = 0; kk < BKK; kk++) {
            float ra[8], rb[8];
            #pragma unroll
            for (int i = 0; i < 8; i++) ra[i] = As[kk][tRow + i];
            #pragma unroll
            for (int j = 0; j < 8; j++) rb[j] = Bs[kk][tCol + j];
            #pragma unroll
            for (int i = 0; i < 8; i++)
                #pragma unroll
                for (int j = 0; j < 8; j++) acc[i][j] += ra[i] * rb[j];
        }
        __syncthreads();
    }
    #pragma unroll
    for (int i = 0; i < 8; i++) {
        int gr = blockRow + tRow + i;
        if (gr >= M) break;
        #pragma unroll
        for (int j = 0; j < 8; j++) {
            int gc = blockCol + tCol + j;
            float c = acc[i][j] + bias[gc];
            if (EPI == 1) c += Cin[(size_t)gr * N + gc];
            if (EPI == 2) c = gelu_exact(c);
            Cout[(size_t)gr * N + gc] = c;
        }
    }
}

// ---------------- im2col (patch extraction) ----------------
__global__ void im2col_kernel(const float* __restrict__ x, float* __restrict__ P) {
    int t = blockIdx.x;               // b*196 + p
    int b = t / 196, p = t % 196;
    int py = p / 14, px = p % 14;
    for (int d = threadIdx.x; d < Dm; d += 256) {
        int c = d >> 8, r = (d >> 4) & 15, col = d & 15;
        P[(size_t)t * Dm + d] =
            x[(((size_t)b * 3 + c) * 224 + py * 16 + r) * 224 + px * 16 + col];
    }
}

__global__ void transpose_kernel(const float* __restrict__ W, float* __restrict__ Wt) {
    int i = blockIdx.x * 256 + threadIdx.x;
    if (i < Dm * Dm) { int o = i / Dm, k = i % Dm; Wt[k * Dm + o] = W[i]; }
}

__global__ void assemble_kernel(const float* __restrict__ P, const float* __restrict__ cls,
                                const float* __restrict__ pos, float* __restrict__ X) {
    int t = blockIdx.x; int b = t / NTOK, n = t % NTOK;
    float* xr = X + (size_t)t * Dm;
    const float* pr = pos + (size_t)n * Dm;
    if (n == 0) {
        for (int d = threadIdx.x; d < Dm; d += 256) xr[d] = cls[d] + pr[d];
    } else {
        const float* pp = P + ((size_t)(b * 196 + n - 1)) * Dm;
        for (int d = threadIdx.x; d < Dm; d += 256) xr[d] = pp[d] + pr[d];
    }
}

// ---------------- LayerNorm (768) ----------------
__global__ void ln_kernel(const float* __restrict__ X, const float* __restrict__ g,
                          const float* __restrict__ bt, float* __restrict__ Y) {
    __shared__ float red[8];
    __shared__ float stat[2];
    int t = blockIdx.x, tid = threadIdx.x;
    const float* xr = X + (size_t)t * Dm;
    float v0 = xr[tid], v1 = xr[tid + 256], v2 = xr[tid + 512];
    float s = warp_sum(v0 + v1 + v2);
    if ((tid & 31) == 0) red[tid >> 5] = s;
    __syncthreads();
    if (tid < 8) {
        float r = red[tid];
        #pragma unroll
        for (int o = 4; o; o >>= 1) r += __shfl_xor_sync(0xFFu, r, o);
        if (tid == 0) stat[0] = r * (1.f / 768.f);
    }
    __syncthreads();
    float m = stat[0];
    float d0 = v0 - m, d1 = v1 - m, d2 = v2 - m;
    float q = warp_sum(d0 * d0 + d1 * d1 + d2 * d2);
    if ((tid & 31) == 0) red[tid >> 5] = q;
    __syncthreads();
    if (tid < 8) {
        float r = red[tid];
        #pragma unroll
        for (int o = 4; o; o >>= 1) r += __shfl_xor_sync(0xFFu, r, o);
        if (tid == 0) stat[1] = rsqrtf(r * (1.f / 768.f) + 1e-6f);
    }
    __syncthreads();
    float rs = stat[1];
    float* yr = Y + (size_t)t * Dm;
    yr[tid]       = d0 * rs * g[tid]       + bt[tid];
    yr[tid + 256] = d1 * rs * g[tid + 256] + bt[tid + 256];
    yr[tid + 512] = d2 * rs * g[tid + 512] + bt[tid + 512];
}

// ---------------- fused attention (one block per (b,h)) ----------------
// smem: Ks[N][68] (padded, float4-friendly, conflict-free), Vs[N][64], qs[8][64], ps[8][N]
__global__ void attn_kernel(const float* __restrict__ QKV, float* __restrict__ O, int N) {
    extern __shared__ float sm[];
    float* Ks = sm;                      // N*68
    float* Vs = Ks + N * 68;             // N*64
    float* qs = Vs + N * 64;             // 8*64
    float* ps = qs + 8 * 64;             // 8*N
    int b = blockIdx.x / Hh, h = blockIdx.x % Hh;
    int tid = threadIdx.x, w = tid >> 5, lane = tid & 31;
    const float* base = QKV + (size_t)b * N * (3 * Dm);
    for (int idx = tid; idx < N * 64; idx += 256) {
        int n = idx >> 6, d = idx & 63;
        Ks[n * 68 + d] = base[(size_t)n * (3 * Dm) + Dm + h * 64 + d];
        Vs[idx]        = base[(size_t)n * (3 * Dm) + 2 * Dm + h * 64 + d];
    }
    __syncthreads();
    const float4* q4 = (const float4*)(qs + w * 64);
    for (int q = w; q < N; q += 8) {
        const float* qp = base + (size_t)q * (3 * Dm) + h * 64;
        qs[w * 64 + lane]      = qp[lane]      * 0.125f;   // DH^-0.5
        qs[w * 64 + lane + 32] = qp[lane + 32] * 0.125f;
        __syncwarp();
        float lmax = -3e38f;
        for (int j = lane; j < N; j += 32) {
            const float4* k4 = (const float4*)(Ks + j * 68);
            float s = 0.f;
            #pragma unroll
            for (int d = 0; d < 16; d++) {
                float4 a = q4[d], kv = k4[d];
                s += a.x * kv.x + a.y * kv.y + a.z * kv.z + a.w * kv.w;
            }
            ps[w * N + j] = s;
            lmax = fmaxf(lmax, s);
        }
        #pragma unroll
        for (int o = 16; o; o >>= 1) lmax = fmaxf(lmax, __shfl_xor_sync(0xFFFFFFFFu, lmax, o));
        __syncwarp();
        float lsum = 0.f;
        for (int j = lane; j < N; j += 32) {
            float e = expf(ps[w * N + j] - lmax);
            ps[w * N + j] = e;
            lsum += e;
        }
        lsum = warp_sum(lsum);
        float inv = 1.f / lsum;
        __syncwarp();
        float a0 = 0.f, a1 = 0.f;
        for (int j = 0; j < N; j++) {
            float pj = ps[w * N + j];
            a0 += pj * Vs[j * 64 + lane];
            a1 += pj * Vs[j * 64 + lane + 32];
        }
        float* op = O + ((size_t)(b * N + q)) * Dm + h * 64;
        op[lane]      = a0 * inv;
        op[lane + 32] = a1 * inv;
        __syncwarp();
    }
}

// ---------------- token selector (LN -> 128 -> GELU -> 1) ----------------
__global__ void selector_kernel(const float* __restrict__ X, const float* __restrict__ g,
                                const float* __restrict__ bt, const float* __restrict__ w1,
                                const float* __restrict__ b1, const float* __restrict__ w2,
                                const float* __restrict__ b2, float* __restrict__ scores) {
    __shared__ float hsm[768];
    __shared__ float red[4];
    __shared__ float stat[2];
    int t = blockIdx.x, tid = threadIdx.x;
    const float* xr = X + (size_t)t * Dm;
    float v[6];
    #pragma unroll
    for (int i = 0; i < 6; i++) v[i] = xr[tid + i * 128];
    float s = 0.f;
    #pragma unroll
    for (int i = 0; i < 6; i++) s += v[i];
    s = warp_sum(s);
    if ((tid & 31) == 0) red[tid >> 5] = s;
    __syncthreads();
    if (tid == 0) stat[0] = (red[0] + red[1] + red[2] + red[3]) * (1.f / 768.f);
    __syncthreads();
    float m = stat[0], q = 0.f;
    #pragma unroll
    for (int i = 0; i < 6; i++) { float d = v[i] - m; q += d * d; }
    q = warp_sum(q);
    if ((tid & 31) == 0) red[tid >> 5] = q;
    __syncthreads();
    if (tid == 0) stat[1] = rsqrtf((red[0] + red[1] + red[2] + red[3]) * (1.f / 768.f) + 1e-6f);
    __syncthreads();
    float rs = stat[1];
    #pragma unroll
    for (int i = 0; i < 6; i++)
        hsm[tid + i * 128] = (v[i] - m) * rs * g[tid + i * 128] + bt[tid + i * 128];
    __syncthreads();
    float acc = b1[tid];
    for (int k = 0; k < 768; k++) acc += hsm[k] * w1[k * 128 + tid];
    float gl = gelu_exact(acc) * w2[tid];
    gl = warp_sum(gl);
    if ((tid & 31) == 0) red[tid >> 5] = gl;
    __syncthreads();
    if (tid == 0) scores[t] = red[0] + red[1] + red[2] + red[3] + b2[0];
}

// ---------------- top-64 per batch (iterative argmax, tie -> lower index) ----------------
__global__ void topk_kernel(const float* __restrict__ scores, int* __restrict__ idx) {
    __shared__ float sv[196];
    __shared__ float rv[256];
    __shared__ int ri[256];
    int b = blockIdx.x, tid = threadIdx.x;
    if (tid < 196) sv[tid] = scores[b * NTOK + 1 + tid];
    if (tid == 0) idx[b * NSEL] = 0;
    __syncthreads();
    for (int it = 0; it < Kk; it++) {
        rv[tid] = (tid < 196) ? sv[tid] : -3e38f;
        ri[tid] = tid;
        __syncthreads();
        for (int s2 = 128; s2 > 0; s2 >>= 1) {
            if (tid < s2) {
                if (rv[tid + s2] > rv[tid] ||
                    (rv[tid + s2] == rv[tid] && ri[tid + s2] < ri[tid])) {
                    rv[tid] = rv[tid + s2];
                    ri[tid] = ri[tid + s2];
                }
            }
            __syncthreads();
        }
        if (tid == 0) { idx[b * NSEL + 1 + it] = ri[0] + 1; sv[ri[0]] = -3e38f; }
        __syncthreads();
    }
}

__global__ void gather_kernel(const float* __restrict__ X, const int* __restrict__ idx,
                              float* __restrict__ Xr) {
    int t = blockIdx.x;
    int b = t / NSEL;
    int src = idx[t];
    const float* s = X + ((size_t)b * NTOK + src) * Dm;
    float* d = Xr + (size_t)t * Dm;
    for (int i = threadIdx.x; i < Dm; i += 256) d[i] = s[i];
}

// ---------------- final LN(CLS) + head ----------------
__global__ void head_kernel(const float* __restrict__ Xr, const float* __restrict__ g,
                            const float* __restrict__ bt, const float* __restrict__ hw,
                            const float* __restrict__ hb, float* __restrict__ out) {
    __shared__ float hsm[768];
    __shared__ float red[8];
    __shared__ float stat[2];
    int b = blockIdx.x, tid = threadIdx.x;
    const float* xr = Xr + (size_t)b * NSEL * Dm;   // token 0
    float v0 = xr[tid], v1 = xr[tid + 256], v2 = xr[tid + 512];
    float s = warp_sum(v0 + v1 + v2);
    if ((tid & 31) == 0) red[tid >> 5] = s;
    __syncthreads();
    if (tid < 8) {
        float r = red[tid];
        #pragma unroll
        for (int o = 4; o; o >>= 1) r += __shfl_xor_sync(0xFFu, r, o);
        if (tid == 0) stat[0] = r * (1.f / 768.f);
    }
    __syncthreads();
    float m = stat[0];
    float d0 = v0 - m, d1 = v1 - m, d2 = v2 - m;
    float q = warp_sum(d0 * d0 + d1 * d1 + d2 * d2);
    if ((tid & 31) == 0) red[tid >> 5] = q;
    __syncthreads();
    if (tid < 8) {
        float r = red[tid];
        #pragma unroll
        for (int o = 4; o; o >>= 1) r += __shfl_xor_sync(0xFFu, r, o);
        if (tid == 0) stat[1] = rsqrtf(r * (1.f / 768.f) + 1e-6f);
    }
    __syncthreads();
    float rs = stat[1];
    hsm[tid]       = d0 * rs * g[tid]       + bt[tid];
    hsm[tid + 256] = d1 * rs * g[tid + 256] + bt[tid + 256];
    hsm[tid + 512] = d2 * rs * g[tid + 512] + bt[tid + 512];
    __syncthreads();
    for (int c = 0; c < 10; c++) {
        float a = 0.f;
        for (int k = tid; k < 768; k += 256) a += hsm[k] * hw[k * 10 + c];
        a = warp_sum(a);
        if ((tid & 31) == 0) red[tid >> 5] = a;
        __syncthreads();
        if (tid == 0) {
            float r = 0.f;
            #pragma unroll
            for (int i = 0; i < 8; i++) r += red[i];
            out[b * 10 + c] = r + hb[c];
        }
        __syncthreads();
    }
}

// ---------------- host orchestration ----------------
extern "C" void kernel_launch(void* const* d_in, const int* in_sizes, int n_in,
                              void* d_out, int out_size) {
    const float* x        = (const float*)d_in[0];
    const float* patch_w  = (const float*)d_in[1];
    const float* patch_b  = (const float*)d_in[2];
    const float* cls_tok  = (const float*)d_in[3];
    const float* pos_emb  = (const float*)d_in[4];
    const float* ln1_g    = (const float*)d_in[5];
    const float* ln1_b    = (const float*)d_in[6];
    const float* qkv_w    = (const float*)d_in[7];
    const float* qkv_b    = (const float*)d_in[8];
    const float* proj_w   = (const float*)d_in[9];
    const float* proj_b   = (const float*)d_in[10];
    const float* ln2_g    = (const float*)d_in[11];
    const float* ln2_b    = (const float*)d_in[12];
    const float* fc1_w    = (const float*)d_in[13];
    const float* fc1_b    = (const float*)d_in[14];
    const float* fc2_w    = (const float*)d_in[15];
    const float* fc2_b    = (const float*)d_in[16];
    const float* sel_ln_g = (const float*)d_in[17];
    const float* sel_ln_b = (const float*)d_in[18];
    const float* sel_w1   = (const float*)d_in[19];
    const float* sel_b1   = (const float*)d_in[20];
    const float* sel_w2   = (const float*)d_in[21];
    const float* sel_b2   = (const float*)d_in[22];
    const float* norm_g   = (const float*)d_in[23];
    const float* norm_b   = (const float*)d_in[24];
    const float* head_w   = (const float*)d_in[25];
    const float* head_b   = (const float*)d_in[26];
    float* out = (float*)d_out;

    float *pX, *pH, *pQKV, *pF1, *pWt, *pScores, *pXr;
    int* pIdx;
    cudaGetSymbolAddress((void**)&pX, g_X);
    cudaGetSymbolAddress((void**)&pH, g_Hbuf);
    cudaGetSymbolAddress((void**)&pQKV, g_QKV);
    cudaGetSymbolAddress((void**)&pF1, g_F1);
    cudaGetSymbolAddress((void**)&pWt, g_Wt);
    cudaGetSymbolAddress((void**)&pScores, g_scores);
    cudaGetSymbolAddress((void**)&pIdx, g_idx);
    cudaGetSymbolAddress((void**)&pXr, g_Xr);

    cudaFuncSetAttribute(attn_kernel, cudaFuncAttributeMaxDynamicSharedMemorySize, 132 * 1024);

    // patch embed: im2col -> GEMM -> assemble(+cls, +pos)
    im2col_kernel<<<Bb * 196, 256>>>(x, pQKV);
    transpose_kernel<<<(Dm * Dm + 255) / 256, 256>>>(patch_w, pWt);
    {
        dim3 grid(Dm / BN, (Bb * 196 + BM - 1) / BM);
        sgemm_kernel<0><<<grid, 256>>>(pQKV, pWt, patch_b, nullptr, pF1, Bb * 196, Dm, Dm);
    }
    assemble_kernel<<<Bb * NTOK, 256>>>(pF1, cls_tok, pos_emb, pX);

    for (int i = 0; i < DEPTH; i++) {
        const int N = (i < WARM) ? NTOK : NSEL;
        float* Xc = (i < WARM) ? pX : pXr;
        const int M = Bb * N;
        dim3 gQKV(3 * Dm / BN, (M + BM - 1) / BM);
        dim3 gD(Dm / BN, (M + BM - 1) / BM);
        dim3 gMLP(MLPD / BN, (M + BM - 1) / BM);

        ln_kernel<<<M, 256>>>(Xc, ln1_g + (size_t)i * Dm, ln1_b + (size_t)i * Dm, pH);
        sgemm_kernel<0><<<gQKV, 256>>>(pH, qkv_w + (size_t)i * Dm * 3 * Dm,
                                       qkv_b + (size_t)i * 3 * Dm, nullptr, pQKV, M, 3 * Dm, Dm);
        size_t smem = ((size_t)N * 68 + (size_t)N * 64 + 8 * 64 + 8 * (size_t)N) * sizeof(float);
        attn_kernel<<<Bb * Hh, 256, smem>>>(pQKV, pH, N);
        sgemm_kernel<1><<<gD, 256>>>(pH, proj_w + (size_t)i * Dm * Dm,
                                     proj_b + (size_t)i * Dm, Xc, Xc, M, Dm, Dm);
        ln_kernel<<<M, 256>>>(Xc, ln2_g + (size_t)i * Dm, ln2_b + (size_t)i * Dm, pH);
        sgemm_kernel<2><<<gMLP, 256>>>(pH, fc1_w + (size_t)i * Dm * MLPD,
                                       fc1_b + (size_t)i * MLPD, nullptr, pF1, M, MLPD, Dm);
        sgemm_kernel<1><<<gD, 256>>>(pF1, fc2_w + (size_t)i * MLPD * Dm,
                                     fc2_b + (size_t)i * Dm, Xc, Xc, M, Dm, MLPD);

        if (i == WARM - 1) {
            selector_kernel<<<Bb * NTOK, 128>>>(pX, sel_ln_g, sel_ln_b, sel_w1, sel_b1,
                                                sel_w2, sel_b2, pScores);
            topk_kernel<<<Bb, 256>>>(pScores, pIdx);
            gather_kernel<<<Bb * NSEL, 256>>>(pX, pIdx, pXr);
        }
    }

    head_kernel<<<Bb, 256>>>(pXr, norm_g, norm_b, head_w, head_b, out);
}